// round 4
// baseline (speedup 1.0000x reference)
#include <cuda_runtime.h>
#include <math.h>

// ---------------- fixed CT geometry ----------------
#define IMG   512
#define NDET  768
#define NV    360

#define PIXd  0.7433
#define DSOd  595.0
#define DSDd  1085.6              // 595.0 + 490.6
#define DETd  1.2858
#define DGd   (DETd / DSDd)       // equiangular pitch (rad/bin)
#define INVDGd (DSDd / DETd)
#define SCALEd (DGd * 2.0 * M_PI / 360.0)   // fold q*=DGAMMA and *=2pi/NV

// padded q row: [16 zero | 768 data | 16 zero]  (i0 in [-12,778] always in-row)
#define QPAD   16
#define QSTRIDE 800

// ---------------- device scratch (no allocations allowed) ----------------
__device__ float2 cs_tab[NV];               // (cos beta, sin beta), double-accurate
__device__ float4 q_pack[NV * QSTRIDE];     // (q0, dq0, q1, dq1), zero-padded

// ---------------- filtering: cosine weight + folded odd-tap ramp conv -----
// g(n) is even and zero at even n!=0:  q[t] = p[t]g0 + sum_e (p[t-d]+p[t+d])*g(d),
// d = 2e+1.  p zero-padded in smem so edges need no branches.
__global__ void __launch_bounds__(NDET) filter_kernel(const float* __restrict__ proj) {
    __shared__ float2 pp[2302];             // 767 zero | 768 data | 767 zero
    __shared__ float  go[NDET / 2];         // go[e] = g(2e+1)
    __shared__ float2 q2[NDET];

    const int v = blockIdx.x;
    const int t = threadIdx.x;

    if (t == 0) {                            // exact view angle, hidden under conv
        double sb, cb;
        sincospi((double)v / 180.0, &sb, &cb);
        cs_tab[v] = make_float2((float)cb, (float)sb);
    }
    if (t < 16) {                            // zero the q_pack pads for this view
        q_pack[v * QSTRIDE + t]              = make_float4(0.f, 0.f, 0.f, 0.f);
        q_pack[v * QSTRIDE + QPAD + NDET + t] = make_float4(0.f, 0.f, 0.f, 0.f);
    }
    if (t < 767) {                           // zero pads of p (disjoint from fill)
        pp[t]        = make_float2(0.f, 0.f);
        pp[1535 + t] = make_float2(0.f, 0.f);
    }
    if (t < NDET / 2) {                      // odd-tap ramp values (fp32 ok: 2e-7)
        float s = sinf((float)(2 * t + 1) * (float)DGd) * (float)M_PI;
        go[t] = (float)(-0.5 * SCALEd) / (s * s);
    }

    float gam = ((float)t - 383.5f) * (float)DGd;
    float cw  = 595.0f * cosf(gam);          // DSO * cos(gamma)
    pp[767 + t] = make_float2(proj[(0 * NV + v) * NDET + t] * cw,
                              proj[(1 * NV + v) * NDET + t] * cw);
    __syncthreads();

    const float g0 = (float)(SCALEd / (8.0 * DGd * DGd));
    float2 pc = pp[767 + t];
    float a0 = pc.x * g0;
    float a1 = pc.y * g0;
#pragma unroll 4
    for (int e = 0; e < NDET / 2; ++e) {
        int   d  = 2 * e + 1;
        float gv = go[e];                    // broadcast
        float2 l = pp[767 + t - d];          // conflict-free
        float2 r = pp[767 + t + d];
        a0 = fmaf(l.x + r.x, gv, a0);
        a1 = fmaf(l.y + r.y, gv, a1);
    }
    q2[t] = make_float2(a0, a1);
    __syncthreads();

    int dn = min(t + 1, NDET - 1);           // last entry: delta only used at w=0
    float2 qa = q2[t], qb = q2[dn];
    q_pack[v * QSTRIDE + QPAD + t] = make_float4(qa.x, qb.x - qa.x, qa.y, qb.y - qa.y);
}

// ---------------- backprojection: 1 thread = 1 pixel, both batches --------
// atan(t) = t*P(t^2), degree-11 Chebyshev on |t|<=0.5059 (all FOV pixels);
// 1/DGAMMA folded into coefficients. Padded q rows remove the index clamp.
__global__ void __launch_bounds__(128, 14) bp_kernel(float* __restrict__ out) {
    __shared__ float2 cs_s[NV];
    const int tid = threadIdx.y * 16 + threadIdx.x;
    for (int s = tid; s < NV; s += 128) cs_s[s] = cs_tab[s];
    __syncthreads();

    const int j = (blockIdx.x << 4) + threadIdx.x;   // column -> x
    const int i = (blockIdx.y << 3) + threadIdx.y;   // row    -> y

    const float x = ((float)j - 255.5f) * (float)PIXd;
    const float y = ((float)i - 255.5f) * (float)PIXd;
    const float DSOf = 595.0f;
    const float R2 = fmaf(x, x, fmaf(y, y, DSOf * DSOf));

    const float B0 = (float)( 1.00000000 * INVDGd);
    const float B1 = (float)(-0.33332973 * INVDGd);
    const float B2 = (float)( 0.19987850 * INVDGd);
    const float B3 = (float)(-0.14115230 * INVDGd);
    const float B4 = (float)( 0.09916330 * INVDGd);
    const float B5 = (float)(-0.04772060 * INVDGd);

    float acc0 = 0.0f, acc1 = 0.0f;
    const float4* __restrict__ qrow = q_pack + QPAD;

#pragma unroll 4
    for (int v = 0; v < NV; ++v) {
        float2 cs = cs_s[v];
        float u  = fmaf(cs.x, x,  cs.y * y);         // cb*x + sb*y
        float cr = fmaf(cs.y, x, -cs.x * y);         // sb*x - cb*y
        float dt = DSOf - u;                         // > 0 for all FOV pixels
        float L2 = fmaf(-2.0f * DSOf, u, R2);        // vx^2 + vy^2
        float tq = __fdividef(cr, dt);
        float s2 = tq * tq;
        float p  = fmaf(B5, s2, B4);
        p = fmaf(p, s2, B3);
        p = fmaf(p, s2, B2);
        p = fmaf(p, s2, B1);
        p = fmaf(p, s2, B0);
        float g  = fmaf(tq, p, 383.5f);              // detector index
        int   i0 = __float2int_rd(g);                // in [-12, 778]: padded row
        float w  = g - __int2float_rn(i0);
        float wl = (fabsf(g - 383.5f) <= 383.5f) ? __fdividef(1.0f, L2) : 0.0f;

        float4 q = qrow[v * QSTRIDE + i0];           // one LDG.128, never OOB
        acc0 = fmaf(fmaf(w, q.y, q.x), wl, acc0);    // q.y/q.w pre-differenced
        acc1 = fmaf(fmaf(w, q.w, q.z), wl, acc1);
    }

    out[i * IMG + j]             = acc0;
    out[IMG * IMG + i * IMG + j] = acc1;
}

// ---------------- entry point ----------------
extern "C" void kernel_launch(void* const* d_in, const int* in_sizes, int n_in,
                              void* d_out, int out_size) {
    (void)in_sizes; (void)n_in; (void)out_size;
    const float* proj = (const float*)d_in[0];   // [2, 360, 768] f32
    float* out = (float*)d_out;                  // [2, 512, 512] f32

    filter_kernel<<<NV, NDET>>>(proj);
    bp_kernel<<<dim3(IMG / 16, IMG / 8), dim3(16, 8)>>>(out);
}

// round 6
// speedup vs baseline: 1.4546x; 1.4546x over previous
#include <cuda_runtime.h>
#include <math.h>

// ---------------- fixed CT geometry ----------------
#define IMG   512
#define NDET  768
#define NV    360
#define GLEN  (2*NDET-1)

#define PIXd  0.7433
#define DSOd  595.0
#define DSDd  1085.6              // 595.0 + 490.6
#define DETd  1.2858
#define DGd   (DETd / DSDd)       // equiangular pitch (rad/bin)
#define INVDGd (DSDd / DETd)
#define SCALEd (DGd * 2.0 * M_PI / 360.0)   // fold q*=DGAMMA and *=2pi/NV

// padded q row: [16 zero | 768 data | 16 zero]; i0 in [-13,779] stays in-row
#define QPAD    16
#define QSTRIDE 800

// sin(383.5 * DGAMMA): in-bounds test done directly on sin(theta)
#define SBOUND 0.4387604f

// ---------------- device scratch (no allocations allowed) ----------------
__device__ float2 cs_tab[NV];               // (cos beta, sin beta)
__device__ float4 q_pack[NV * QSTRIDE];     // (q0, dq0, q1, dq1), zero-padded
__device__ float  part_img[2 * IMG * IMG];  // partner-half contributions

// ---------------- filtering (round-3 proven form) --------------------------
__global__ void __launch_bounds__(NDET) filter_kernel(const float* __restrict__ proj) {
    __shared__ float2 p2[NDET];
    __shared__ float  gs[GLEN];
    __shared__ float2 q2[NDET];

    const int v = blockIdx.x;
    const int t = threadIdx.x;

    if (t == 0) {
        double sb, cb;
        sincospi((double)v / 180.0, &sb, &cb);
        cs_tab[v] = make_float2((float)cb, (float)sb);
    }
    if (t < QPAD) {                          // zero this view's q_pack pads
        q_pack[v * QSTRIDE + t]               = make_float4(0.f, 0.f, 0.f, 0.f);
        q_pack[v * QSTRIDE + QPAD + NDET + t] = make_float4(0.f, 0.f, 0.f, 0.f);
    }
    for (int i = t; i < GLEN; i += NDET) {   // ramp taps (fp32: 2e-7 rel)
        int n = i - (NDET - 1);
        float g;
        if (n == 0) {
            g = (float)(SCALEd / (8.0 * DGd * DGd));
        } else if (n & 1) {
            float s = sinf((float)n * (float)DGd) * (float)M_PI;
            g = (float)(-0.5 * SCALEd) / (s * s);
        } else {
            g = 0.0f;
        }
        gs[i] = g;
    }

    float gam = ((float)t - 383.5f) * (float)DGd;
    float cw  = 595.0f * cosf(gam);
    p2[t] = make_float2(proj[(0 * NV + v) * NDET + t] * cw,
                        proj[(1 * NV + v) * NDET + t] * cw);
    __syncthreads();

    float2 pc = p2[t];
    float g0  = gs[NDET - 1];
    float a0 = pc.x * g0;
    float a1 = pc.y * g0;
    const int k0 = (t + 1) & 1;
#pragma unroll 8
    for (int k = k0; k < NDET; k += 2) {
        float gv = gs[t - k + (NDET - 1)];
        float2 p = p2[k];                    // broadcast LDS.64
        a0 = fmaf(p.x, gv, a0);
        a1 = fmaf(p.y, gv, a1);
    }
    q2[t] = make_float2(a0, a1);
    __syncthreads();

    int dn = min(t + 1, NDET - 1);
    float2 qa = q2[t], qb = q2[dn];
    q_pack[v * QSTRIDE + QPAD + t] = make_float4(qa.x, qb.x - qa.x, qa.y, qb.y - qa.y);
}

// ---------------- backprojection with view-conjugacy -----------------------
// geom(P, beta) == geom(-P, beta+pi): one geometry serves pixel P at view v
// (q row v) and pixel P' = (511-i, 511-j) at view v+180 (q row v+180).
// theta = asin(cr * rsqrt(L2)); degree-15 Taylor; 1/DGAMMA folded in.
__global__ void __launch_bounds__(256, 6) bp_kernel(float* __restrict__ out) {
    __shared__ float2 cs_s[NV / 2];
    const int tid = threadIdx.y * 16 + threadIdx.x;
    if (tid < NV / 2) cs_s[tid] = cs_tab[tid];
    __syncthreads();

    const int j = (blockIdx.x << 4) + threadIdx.x;
    const int i = (blockIdx.y << 4) + threadIdx.y;

    const float x = ((float)j - 255.5f) * (float)PIXd;
    const float y = ((float)i - 255.5f) * (float)PIXd;
    const float DSOf = 595.0f;

    // asin Taylor coefficients * (1/DGAMMA)
    const float A0 = (float)(INVDGd);
    const float A1 = (float)(INVDGd / 6.0);
    const float A2 = (float)(INVDGd * 0.075);
    const float A3 = (float)(INVDGd * 0.044642857);
    const float A4 = (float)(INVDGd * 0.030381944);
    const float A5 = (float)(INVDGd * 0.022372159);
    const float A6 = (float)(INVDGd * 0.017352764);
    const float A7 = (float)(INVDGd * 0.013964844);

    float accS0 = 0.f, accS1 = 0.f;          // this pixel, views 0..179
    float accP0 = 0.f, accP1 = 0.f;          // partner pixel, views 180..359

    const float4* __restrict__ qp = q_pack + QPAD;

#pragma unroll 4
    for (int v = 0; v < NV / 2; ++v) {
        float2 cs = cs_s[v];
        float u  = fmaf(cs.x, x,  cs.y * y);
        float cr = fmaf(cs.y, x, -cs.x * y);
        float dt = DSOf - u;
        float L2 = fmaf(dt, dt, cr * cr);
        float rsq;
        asm("rsqrt.approx.f32 %0, %1;" : "=f"(rsq) : "f"(L2));
        float s  = cr * rsq;                 // sin(theta), dt > 0 always
        float s2 = s * s;
        float p  = fmaf(A7, s2, A6);
        p = fmaf(p, s2, A5);
        p = fmaf(p, s2, A4);
        p = fmaf(p, s2, A3);
        p = fmaf(p, s2, A2);
        p = fmaf(p, s2, A1);
        p = fmaf(p, s2, A0);
        float g  = fmaf(s, p, 383.5f);       // detector index in [-12.2, 779.2]

        float T  = (g - 0.5f) + 12582912.0f; // round(g-0.5) ~= floor(g)
        int   i0 = __float_as_int(T) - 0x4B400000;
        float fg = T - 12582912.0f;
        float w  = g - fg;                   // off-by-one at ties is harmless
        float m  = rsq * rsq;                // 1/L2
        float wl = (fabsf(s) <= SBOUND) ? m : 0.0f;

        const float4* qv = qp + v * QSTRIDE + i0;
        float4 qa = qv[0];                   // view v        (self)
        float4 qb = qv[(NV / 2) * QSTRIDE];  // view v+180    (partner)
        accS0 = fmaf(fmaf(w, qa.y, qa.x), wl, accS0);
        accS1 = fmaf(fmaf(w, qa.w, qa.z), wl, accS1);
        accP0 = fmaf(fmaf(w, qb.y, qb.x), wl, accP0);
        accP1 = fmaf(fmaf(w, qb.w, qb.z), wl, accP1);
    }

    out[i * IMG + j]             = accS0;
    out[IMG * IMG + i * IMG + j] = accS1;
    const int pi = (IMG - 1) - i, pj = (IMG - 1) - j;
    part_img[pi * IMG + pj]             = accP0;
    part_img[IMG * IMG + pi * IMG + pj] = accP1;
}

// ---------------- combine: out += partner image ---------------------------
__global__ void __launch_bounds__(512) combine_kernel(float* __restrict__ out) {
    int t = blockIdx.x * 512 + threadIdx.x;          // float4 index
    float4* o = (float4*)out;
    const float4* p = (const float4*)part_img;
    float4 a = o[t], b = p[t];
    o[t] = make_float4(a.x + b.x, a.y + b.y, a.z + b.z, a.w + b.w);
}

// ---------------- entry point ----------------
extern "C" void kernel_launch(void* const* d_in, const int* in_sizes, int n_in,
                              void* d_out, int out_size) {
    (void)in_sizes; (void)n_in; (void)out_size;
    const float* proj = (const float*)d_in[0];   // [2, 360, 768] f32
    float* out = (float*)d_out;                  // [2, 512, 512] f32

    filter_kernel<<<NV, NDET>>>(proj);
    bp_kernel<<<dim3(IMG / 16, IMG / 16), dim3(16, 16)>>>(out);
    combine_kernel<<<(2 * IMG * IMG / 4) / 512, 512>>>(out);
}

// round 7
// speedup vs baseline: 1.6376x; 1.1259x over previous
#include <cuda_runtime.h>
#include <math.h>

// ---------------- fixed CT geometry ----------------
#define IMG   512
#define NDET  768
#define NV    360
#define GLEN  (2*NDET-1)

#define PIXd  0.7433
#define DSOd  595.0
#define DSDd  1085.6              // 595.0 + 490.6
#define DETd  1.2858
#define DGd   (DETd / DSDd)       // equiangular pitch (rad/bin)
#define INVDGd (DSDd / DETd)
#define SCALEd (DGd * 2.0 * M_PI / 360.0)   // fold q*=DGAMMA and *=2pi/NV

// padded q row: [16 zero | 768 data | 16 zero]; i0 in [-13,779] stays in-row
#define QPAD    16
#define QSTRIDE 800

// ---------------- device scratch (no allocations allowed) ----------------
__device__ float2 cs_tab[NV];               // (cos beta, sin beta)
__device__ float4 q_pack[NV * QSTRIDE];     // (q0, dq0, q1, dq1), zero-padded
__device__ float  part_img[3][2 * IMG * IMG]; // rot-90/180/270 contributions

// ---------------- filtering: 2 outputs/thread, shared p loads -------------
__global__ void __launch_bounds__(384) filter_kernel(const float* __restrict__ proj) {
    __shared__ float2 p2[NDET];
    __shared__ float  gs[GLEN];
    __shared__ float2 q2[NDET];

    const int v = blockIdx.x;
    const int t = threadIdx.x;               // output pair: t and t+384

    if (t == 0) {
        double sb, cb;
        sincospi((double)v / 180.0, &sb, &cb);
        cs_tab[v] = make_float2((float)cb, (float)sb);
    }
    if (t < QPAD) {                          // zero this view's q_pack pads
        q_pack[v * QSTRIDE + t]               = make_float4(0.f, 0.f, 0.f, 0.f);
        q_pack[v * QSTRIDE + QPAD + NDET + t] = make_float4(0.f, 0.f, 0.f, 0.f);
    }
    for (int i = t; i < GLEN; i += 384) {    // ramp taps (fp32: 2e-7 rel)
        int n = i - (NDET - 1);
        float g;
        if (n == 0) {
            g = (float)(SCALEd / (8.0 * DGd * DGd));
        } else if (n & 1) {
            float s = sinf((float)n * (float)DGd) * (float)M_PI;
            g = (float)(-0.5 * SCALEd) / (s * s);
        } else {
            g = 0.0f;
        }
        gs[i] = g;
    }
    {   // cosine-weighted projections, 2 detector bins per thread
        float ga = ((float)t - 383.5f) * (float)DGd;
        float gb = ((float)(t + 384) - 383.5f) * (float)DGd;
        float ca = 595.0f * cosf(ga), cb = 595.0f * cosf(gb);
        p2[t]       = make_float2(proj[(0 * NV + v) * NDET + t] * ca,
                                  proj[(1 * NV + v) * NDET + t] * ca);
        p2[t + 384] = make_float2(proj[(0 * NV + v) * NDET + t + 384] * cb,
                                  proj[(1 * NV + v) * NDET + t + 384] * cb);
    }
    __syncthreads();

    const float g0 = gs[NDET - 1];
    float2 pa = p2[t], pb = p2[t + 384];
    float a0 = pa.x * g0, a1 = pa.y * g0;    // output t
    float b0 = pb.x * g0, b1 = pb.y * g0;    // output t+384
    const int k0 = (t + 1) & 1;              // same parity for both outputs
#pragma unroll 8
    for (int k = k0; k < NDET; k += 2) {
        float2 p  = p2[k];                   // shared by both outputs
        float gva = gs[t - k + (NDET - 1)];
        float gvb = gs[t - k + (NDET - 1) + 384];
        a0 = fmaf(p.x, gva, a0);
        a1 = fmaf(p.y, gva, a1);
        b0 = fmaf(p.x, gvb, b0);
        b1 = fmaf(p.y, gvb, b1);
    }
    q2[t]       = make_float2(a0, a1);
    q2[t + 384] = make_float2(b0, b1);
    __syncthreads();

    {
        int dn = t + 1;                      // t <= 383, always valid
        float2 qa = q2[t], qb = q2[dn];
        q_pack[v * QSTRIDE + QPAD + t] =
            make_float4(qa.x, qb.x - qa.x, qa.y, qb.y - qa.y);
        int t2 = t + 384;
        int dn2 = min(t2 + 1, NDET - 1);
        float2 qc = q2[t2], qd = q2[dn2];
        q_pack[v * QSTRIDE + QPAD + t2] =
            make_float4(qc.x, qd.x - qc.x, qc.y, qd.y - qc.y);
    }
}

// ---------------- backprojection with 4-fold rotation symmetry -------------
// geom((x,y), beta) == geom((-y,x), beta+pi/2) == geom((-x,-y), beta+pi)
//                   == geom((y,-x), beta+3pi/2)   (verified exactly).
// One geometry serves 4 pixel-view updates; loop is views 0..89 only.
__global__ void __launch_bounds__(256, 6) bp_kernel(float* __restrict__ out) {
    __shared__ float2 cs_s[NV / 4];
    const int tid = threadIdx.y * 16 + threadIdx.x;
    if (tid < NV / 4) cs_s[tid] = cs_tab[tid];
    __syncthreads();

    const int j = (blockIdx.x << 4) + threadIdx.x;
    const int i = (blockIdx.y << 4) + threadIdx.y;

    const float x = ((float)j - 255.5f) * (float)PIXd;
    const float y = ((float)i - 255.5f) * (float)PIXd;
    const float DSOf = 595.0f;

    // asin Taylor coefficients * (1/DGAMMA)
    const float A0 = (float)(INVDGd);
    const float A1 = (float)(INVDGd / 6.0);
    const float A2 = (float)(INVDGd * 0.075);
    const float A3 = (float)(INVDGd * 0.044642857);
    const float A4 = (float)(INVDGd * 0.030381944);
    const float A5 = (float)(INVDGd * 0.022372159);
    const float A6 = (float)(INVDGd * 0.017352764);
    const float A7 = (float)(INVDGd * 0.013964844);

    float aS0 = 0.f, aS1 = 0.f;              // self pixel,     views 0..89
    float a90_0 = 0.f, a90_1 = 0.f;          // rot +90 pixel,  views 90..179
    float a180_0 = 0.f, a180_1 = 0.f;        // rot 180 pixel,  views 180..269
    float a270_0 = 0.f, a270_1 = 0.f;        // rot 270 pixel,  views 270..359

    const float4* __restrict__ qp = q_pack + QPAD;

#pragma unroll 3
    for (int v = 0; v < NV / 4; ++v) {
        float2 cs = cs_s[v];
        float u  = fmaf(cs.x, x,  cs.y * y);
        float cr = fmaf(cs.y, x, -cs.x * y);
        float dt = DSOf - u;
        float L2 = fmaf(dt, dt, cr * cr);
        float rsq;
        asm("rsqrt.approx.f32 %0, %1;" : "=f"(rsq) : "f"(L2));
        float s  = cr * rsq;                 // sin(theta), dt > 0 always
        float s2 = s * s;
        float p  = fmaf(A7, s2, A6);
        p = fmaf(p, s2, A5);
        p = fmaf(p, s2, A4);
        p = fmaf(p, s2, A3);
        p = fmaf(p, s2, A2);
        p = fmaf(p, s2, A1);
        p = fmaf(p, s2, A0);
        float tv = s * p;                    // g - 383.5 (detector offset)
        float g  = tv + 383.5f;

        float T  = (g - 0.5f) + 12582912.0f; // round(g-0.5) == floor(g)
        int   i0 = __float_as_int(T) - 0x4B400000;
        float fg = T - 12582912.0f;
        float w  = g - fg;
        float m  = rsq * rsq;                // 1/L2
        float wl = (fabsf(tv) <= 383.5f) ? m : 0.0f;   // g in [0,767]

        const float4* qv = qp + v * QSTRIDE + i0;
        float4 qa = qv[0];                          // view v
        float4 qb = qv[ 90 * QSTRIDE];              // view v+90
        float4 qc = qv[180 * QSTRIDE];              // view v+180
        float4 qd = qv[270 * QSTRIDE];              // view v+270
        aS0    = fmaf(fmaf(w, qa.y, qa.x), wl, aS0);
        aS1    = fmaf(fmaf(w, qa.w, qa.z), wl, aS1);
        a90_0  = fmaf(fmaf(w, qb.y, qb.x), wl, a90_0);
        a90_1  = fmaf(fmaf(w, qb.w, qb.z), wl, a90_1);
        a180_0 = fmaf(fmaf(w, qc.y, qc.x), wl, a180_0);
        a180_1 = fmaf(fmaf(w, qc.w, qc.z), wl, a180_1);
        a270_0 = fmaf(fmaf(w, qd.y, qd.x), wl, a270_0);
        a270_1 = fmaf(fmaf(w, qd.w, qd.z), wl, a270_1);
    }

    out[i * IMG + j]             = aS0;
    out[IMG * IMG + i * IMG + j] = aS1;
    // rot +90: pixel (i', j') = (j, 511-i)
    part_img[0][j * IMG + (IMG - 1 - i)]             = a90_0;
    part_img[0][IMG * IMG + j * IMG + (IMG - 1 - i)] = a90_1;
    // rot 180: (511-i, 511-j)
    part_img[1][(IMG - 1 - i) * IMG + (IMG - 1 - j)]             = a180_0;
    part_img[1][IMG * IMG + (IMG - 1 - i) * IMG + (IMG - 1 - j)] = a180_1;
    // rot 270: (511-j, i)
    part_img[2][(IMG - 1 - j) * IMG + i]             = a270_0;
    part_img[2][IMG * IMG + (IMG - 1 - j) * IMG + i] = a270_1;
}

// ---------------- combine: out += s90 + s180 + s270 ------------------------
__global__ void __launch_bounds__(512) combine_kernel(float* __restrict__ out) {
    int t = blockIdx.x * 512 + threadIdx.x;          // float4 index
    float4* o = (float4*)out;
    const float4* p0 = (const float4*)part_img[0];
    const float4* p1 = (const float4*)part_img[1];
    const float4* p2 = (const float4*)part_img[2];
    float4 a = o[t], b = p0[t], c = p1[t], d = p2[t];
    o[t] = make_float4(a.x + b.x + c.x + d.x,
                       a.y + b.y + c.y + d.y,
                       a.z + b.z + c.z + d.z,
                       a.w + b.w + c.w + d.w);
}

// ---------------- entry point ----------------
extern "C" void kernel_launch(void* const* d_in, const int* in_sizes, int n_in,
                              void* d_out, int out_size) {
    (void)in_sizes; (void)n_in; (void)out_size;
    const float* proj = (const float*)d_in[0];   // [2, 360, 768] f32
    float* out = (float*)d_out;                  // [2, 512, 512] f32

    filter_kernel<<<NV, 384>>>(proj);
    bp_kernel<<<dim3(IMG / 16, IMG / 16), dim3(16, 16)>>>(out);
    combine_kernel<<<(2 * IMG * IMG / 4) / 512, 512>>>(out);
}